// round 13
// baseline (speedup 1.0000x reference)
#include <cuda_runtime.h>

#define N_GL    256
#define LTAU    1000
#define BATCH   16
#define NPOLES  16
#define NPAIR   8
#define N_ITEMS 528          /* 16 g0 + 512 gtau */

__device__ float g_phi[N_GL];
__device__ float g_w[N_GL];
__device__ unsigned int g_ctr;

// ---- f32x2 packed helpers (sm_103a) ---------------------------------------
__device__ __forceinline__ unsigned long long pk2(float lo, float hi) {
    unsigned long long r;
    asm("mov.b64 %0,{%1,%2};" : "=l"(r) : "f"(lo), "f"(hi));
    return r;
}
__device__ __forceinline__ void upk2(unsigned long long v, float& lo, float& hi) {
    asm("mov.b64 {%0,%1},%2;" : "=f"(lo), "=f"(hi) : "l"(v));
}
__device__ __forceinline__ unsigned long long fma2(unsigned long long a,
                                                   unsigned long long b,
                                                   unsigned long long c) {
    unsigned long long r;
    asm("fma.rn.f32x2 %0,%1,%2,%3;" : "=l"(r) : "l"(a), "l"(b), "l"(c));
    return r;
}
__device__ __forceinline__ unsigned long long mul2(unsigned long long a,
                                                   unsigned long long b) {
    unsigned long long r;
    asm("mul.rn.f32x2 %0,%1,%2;" : "=l"(r) : "l"(a), "l"(b));
    return r;
}
__device__ __forceinline__ unsigned long long add2(unsigned long long a,
                                                   unsigned long long b) {
    unsigned long long r;
    asm("add.rn.f32x2 %0,%1,%2;" : "=l"(r) : "l"(a), "l"(b));
    return r;
}

// ---------------------------------------------------------------------------
// Kernel A: blocks 0..7 Gauss-Legendre via warp matrix-scan; blocks 8..9 zero
// the output buffer; block 8 also resets the work counter.
// ---------------------------------------------------------------------------
__global__ void __launch_bounds__(512) initzero_kernel(float* __restrict__ out) {
    const int t = threadIdx.x;

    if (blockIdx.x >= 8) {
        if (blockIdx.x == 8 && t == 0) g_ctr = 0u;
        float4* o4 = (float4*)out;
        const float4 z4 = make_float4(0.f, 0.f, 0.f, 0.f);
        for (int i = (blockIdx.x - 8) * 512 + t; i < (BATCH * LTAU) / 4; i += 1024)
            o4[i] = z4;
        return;
    }

    const int lane = t & 31;
    const int wid  = t >> 5;
    const int r    = blockIdx.x * 16 + wid;          // root index 0..127

    const float PI = 3.14159265358979323846f;
    float z = cosf(PI * ((float)r + 0.75f) / 256.5f);

    float Aj[8], Bj[8];
#pragma unroll
    for (int k = 0; k < 8; ++k) {
        float j   = (float)(8 * lane + 1 + k);
        float inv = __fdividef(1.0f, j);
        Aj[k] = 2.0f - inv;
        Bj[k] = 1.0f - inv;
    }

    float p1 = 1.0f, p2 = 0.0f, pp = 1.0f;
    for (int pass = 0; pass < 3; ++pass) {
        float m00 = 1.0f, m01 = 0.0f, m10 = 0.0f, m11 = 1.0f;
#pragma unroll
        for (int k = 0; k < 8; ++k) {
            float a   = Aj[k] * z;
            float n00 = fmaf(a, m00, -Bj[k] * m10);
            float n01 = fmaf(a, m01, -Bj[k] * m11);
            m10 = m00; m11 = m01;
            m00 = n00; m01 = n01;
        }
#pragma unroll
        for (int off = 1; off < 32; off <<= 1) {
            float q00 = __shfl_up_sync(0xffffffffu, m00, off);
            float q01 = __shfl_up_sync(0xffffffffu, m01, off);
            float q10 = __shfl_up_sync(0xffffffffu, m10, off);
            float q11 = __shfl_up_sync(0xffffffffu, m11, off);
            if (lane >= off) {
                float n00 = m00 * q00 + m01 * q10;
                float n01 = m00 * q01 + m01 * q11;
                float n10 = m10 * q00 + m11 * q10;
                float n11 = m10 * q01 + m11 * q11;
                m00 = n00; m01 = n01; m10 = n10; m11 = n11;
            }
        }
        p1 = __shfl_sync(0xffffffffu, m00, 31);
        p2 = __shfl_sync(0xffffffffu, m10, 31);
        pp = 256.0f * (z * p1 - p2) / (z * z - 1.0f);
        z -= p1 / pp;
    }

    if (lane == 0) {
        float wgt = 2.0f / ((1.0f - z * z) * pp * pp);
        float ph  = tanf(0.5f * PI * z);
        g_phi[N_GL - 1 - r] = ph;
        g_phi[r]            = -ph;
        g_w[N_GL - 1 - r]   = wgt;
        g_w[r]              = wgt;
    }
}

// ---------------------------------------------------------------------------
// Kernel B: persistent 444-block grid pulling items from a global counter.
// Items 0..15: Matsubara G0 for batch b=id (owns out[b,0]).
// Items 16..527: gtau (b, nodegroup); warp = one node, private 8KB smem slab,
// f32x2 T/S-fold geometric recurrence, per-warp early exit; block epilogue
// merges 16 slabs and issues 4 REDs per warp slice.
// ---------------------------------------------------------------------------
__global__ void __launch_bounds__(256, 3) main_kernel(
    const float* __restrict__ poles_re,
    const float* __restrict__ poles_im,
    const float* __restrict__ res_re,
    const float* __restrict__ res_im,
    float* __restrict__ out)
{
    extern __shared__ float slab[];   // [8 warps][2048]
    __shared__ float s_pole[64];      // staged b-row: eps | gam | a | b
    __shared__ float s_red[8];
    __shared__ unsigned int s_id;

    const int t    = threadIdx.x;
    const int lane = t & 31;
    const int wid  = t >> 5;

    for (;;) {
        if (t == 0) s_id = atomicAdd(&g_ctr, 1u);
        __syncthreads();
        const unsigned int id = s_id;
        if (id >= N_ITEMS) return;

        if (id >= 16u) {
            // ------------------------- gtau -------------------------------
            const int item = (int)id - 16;
            const int b    = item >> 5;
            const int node = ((item & 31) << 3) + wid;

            // stage this batch's 64 pole floats
            if (t < 64) {
                int p = t & 15;
                int which = t >> 4;
                float v;
                if      (which == 0) v =  poles_re[b * NPOLES + p];
                else if (which == 1) v = -poles_im[b * NPOLES + p];
                else if (which == 2) v =  res_re[b * NPOLES + p];
                else                 v =  res_im[b * NPOLES + p];
                s_pole[t] = v;
            }

            float* myF = slab + wid * 2048;
            float* myB = myF + 1024;

            // zero own slab
            {
                float4* s4 = (float4*)myF;
                const float4 z4 = make_float4(0.f, 0.f, 0.f, 0.f);
#pragma unroll
                for (int i = 0; i < 16; ++i) s4[i * 32 + lane] = z4;
            }
            __syncthreads();

            const float phi = g_phi[node];
            const float w   = g_w[node];

            float Etv[NPOLES], Mv[NPOLES], Rv[NPOLES];
            float s_min = 1e30f;
#pragma unroll
            for (int p = 0; p < NPOLES; ++p) {
                float eps = s_pole[p];
                float gam = s_pole[16 + p];
                float a   = s_pole[32 + p];
                float bb  = s_pole[48 + p];

                float om = fmaf(gam, phi, eps);
                float s  = fabsf(om);
                s_min = fminf(s_min, s);
                float numer = 0.25f * w * fmaf(-bb, phi, a);
                float C = numer / (1.0f + __expf(-10.0f * s));
                bool fwd = (om >= 0.0f);
                Rv[p] = fwd ? 1.0f : -1.0f;
                Mv[p] = __expf(-0.32f * s);
                float k = fwd ? (float)lane : (float)(lane + 1);
                Etv[p] = C * __expf(-0.01f * k * s);
            }
            // chunk dead when 0.32*c*s_min > 16  ->  c > 50/s_min
            int myNeed = min(32, (int)(__fdividef(50.0f, s_min)) + 1);

            unsigned long long Et2[NPAIR], M2[NPAIR], R2[NPAIR];
#pragma unroll
            for (int q = 0; q < NPAIR; ++q) {
                Et2[q] = pk2(Etv[q], Etv[q + 8]);
                M2[q]  = pk2(Mv[q],  Mv[q + 8]);
                R2[q]  = pk2(Rv[q],  Rv[q + 8]);
            }

#pragma unroll 2
            for (int c = 0; c < myNeed; ++c) {
                unsigned long long aT2 = 0ull, aS2 = 0ull;
#pragma unroll
                for (int q = 0; q < NPAIR; ++q) {
                    aT2 = add2(aT2, Et2[q]);
                    aS2 = fma2(R2[q], Et2[q], aS2);
                    Et2[q] = mul2(Et2[q], M2[q]);
                }
                float t0, t1, sx0, sx1;
                upk2(aT2, t0, t1);
                upk2(aS2, sx0, sx1);
                float tt = t0 + t1;
                float ss = sx0 + sx1;
                int idx = (c << 5) + lane;
                myF[idx] = tt + ss;
                myB[idx] = tt - ss;
            }

            __syncthreads();

            // epilogue: warp wid sums 16 slabs over l in [128*wid, +127]
            const int l = (wid << 7) + (lane << 2);
            if (l < LTAU) {
                float ax = 0.f, ay = 0.f, az = 0.f, aw = 0.f;
#pragma unroll
                for (int w2 = 0; w2 < 8; ++w2) {
                    const float* base = slab + w2 * 2048;
                    float4 f  = *(const float4*)(base + l);
                    float4 bq = *(const float4*)(base + 1024 + (996 - l));
                    ax += f.x + bq.w;
                    ay += f.y + bq.z;
                    az += f.z + bq.y;
                    aw += f.w + bq.x;
                }
                if (l == 0) ax = 0.0f;     // l==0 belongs to g0
                float* o = out + b * LTAU + l;
                atomicAdd(o + 0, ax);
                atomicAdd(o + 1, ay);
                atomicAdd(o + 2, az);
                atomicAdd(o + 3, aw);
            }
            __syncthreads();               // slab/smem safe for next item
        } else {
            // ------------------------- g0 ---------------------------------
            const int b = (int)id;

            float eps[NPOLES], gam[NPOLES], av[NPOLES], bv[NPOLES];
            float SRc1 = 0.0f, SRc2 = 0.0f, SIc3 = 0.0f, SRc4 = 0.0f, SIc5 = 0.0f;
#pragma unroll
            for (int p = 0; p < NPOLES; ++p) {
                float e =  poles_re[b * NPOLES + p];
                float g = -poles_im[b * NPOLES + p];
                float a =  res_re[b * NPOLES + p];
                float bb = res_im[b * NPOLES + p];
                eps[p] = e; gam[p] = g; av[p] = a; bv[p] = bb;
                float cr = -a, ci = -bb;
                float r2 = cr * e + ci * g, i2 = ci * e - cr * g;
                float r3 = r2 * e + i2 * g, i3 = i2 * e - r2 * g;
                float r4 = r3 * e + i3 * g, i4 = i3 * e - r3 * g;
                float i5 = i4 * e - r4 * g;
                SRc1 += cr; SRc2 += r2; SIc3 += i3; SRc4 += r4; SIc5 += i5;
            }

            const double PI = 3.14159265358979323846;
            const float wn = (float)((2.0 * (double)t + 1.0) * (PI / 10.0));

            float reS = 0.0f;
#pragma unroll
            for (int p = 0; p < NPOLES; ++p) {
                float d = gam[p] + wn;
                reS += (av[p] * eps[p] - bv[p] * d) / (eps[p] * eps[p] + d * d);
            }
            float iw  = 1.0f / wn;
            float iw2 = iw * iw;
            float reG = reS + iw2 * (SRc2 + SIc3 * iw - SRc4 * iw2 - SIc5 * iw2 * iw);

            float acc = reG;
#pragma unroll
            for (int off = 16; off > 0; off >>= 1)
                acc += __shfl_xor_sync(0xffffffffu, acc, off);
            if (lane == 0) s_red[wid] = acc;
            __syncthreads();
            if (t < 8) {
                float v = s_red[t];
#pragma unroll
                for (int off = 4; off > 0; off >>= 1)
                    v += __shfl_xor_sync(0xffu, v, off);
                if (t == 0) {
                    const float C0 = -0.5f;
                    const float C1 = -2.5f;
                    const float C2 = (float)(-7.0 * 1.2020569031595942 * 100.0 /
                                             (4.0 * PI * PI * PI));
                    const float C3 = (float)(1000.0 / 48.0);
                    const float C4 = (float)(31.0 * 1.0369277551433699 * 10000.0 /
                                             (16.0 * PI * PI * PI * PI * PI));
                    float G0 = C0 * SRc1 + C1 * SRc2 + C2 * SIc3 + C3 * SRc4
                             + C4 * SIc5 + 0.2f * v;
                    out[b * LTAU + 0] = G0;
                }
            }
            __syncthreads();
        }
    }
}

extern "C" void kernel_launch(void* const* d_in, const int* in_sizes, int n_in,
                              void* d_out, int out_size) {
    (void)in_sizes; (void)n_in; (void)out_size;
    const float* pre = (const float*)d_in[0];
    const float* pim = (const float*)d_in[1];
    const float* rre = (const float*)d_in[2];
    const float* rim = (const float*)d_in[3];
    float* out = (float*)d_out;

    static int attr_set = 0;
    if (!attr_set) {
        cudaFuncSetAttribute(main_kernel,
                             cudaFuncAttributeMaxDynamicSharedMemorySize,
                             8 * 2048 * (int)sizeof(float));
        attr_set = 1;
    }

    initzero_kernel<<<10, 512>>>(out);
    main_kernel<<<444, 256, 8 * 2048 * sizeof(float)>>>(pre, pim, rre, rim, out);
}

// round 14
// speedup vs baseline: 1.4305x; 1.4305x over previous
#include <cuda_runtime.h>

#define N_GL    256
#define LTAU    1000
#define BATCH   16
#define NPOLES  16
#define NPAIR   8

__device__ float g_phi[N_GL];
__device__ float g_w[N_GL];

// ---- f32x2 packed helpers (sm_103a) ---------------------------------------
__device__ __forceinline__ unsigned long long pk2(float lo, float hi) {
    unsigned long long r;
    asm("mov.b64 %0,{%1,%2};" : "=l"(r) : "f"(lo), "f"(hi));
    return r;
}
__device__ __forceinline__ void upk2(unsigned long long v, float& lo, float& hi) {
    asm("mov.b64 {%0,%1},%2;" : "=f"(lo), "=f"(hi) : "l"(v));
}
__device__ __forceinline__ unsigned long long fma2(unsigned long long a,
                                                   unsigned long long b,
                                                   unsigned long long c) {
    unsigned long long r;
    asm("fma.rn.f32x2 %0,%1,%2,%3;" : "=l"(r) : "l"(a), "l"(b), "l"(c));
    return r;
}
__device__ __forceinline__ unsigned long long mul2(unsigned long long a,
                                                   unsigned long long b) {
    unsigned long long r;
    asm("mul.rn.f32x2 %0,%1,%2;" : "=l"(r) : "l"(a), "l"(b));
    return r;
}
__device__ __forceinline__ unsigned long long add2(unsigned long long a,
                                                   unsigned long long b) {
    unsigned long long r;
    asm("add.rn.f32x2 %0,%1,%2;" : "=l"(r) : "l"(a), "l"(b));
    return r;
}

// ---------------------------------------------------------------------------
// Kernel A: blocks 0..7 Gauss-Legendre via warp matrix-scan; blocks 8..9 zero
// the output buffer.
// ---------------------------------------------------------------------------
__global__ void __launch_bounds__(512) initzero_kernel(float* __restrict__ out) {
    const int t = threadIdx.x;

    if (blockIdx.x >= 8) {
        float4* o4 = (float4*)out;
        const float4 z4 = make_float4(0.f, 0.f, 0.f, 0.f);
        for (int i = (blockIdx.x - 8) * 512 + t; i < (BATCH * LTAU) / 4; i += 1024)
            o4[i] = z4;
        return;
    }

    const int lane = t & 31;
    const int wid  = t >> 5;
    const int r    = blockIdx.x * 16 + wid;          // root index 0..127

    const float PI = 3.14159265358979323846f;
    float z = cosf(PI * ((float)r + 0.75f) / 256.5f);

    float Aj[8], Bj[8];
#pragma unroll
    for (int k = 0; k < 8; ++k) {
        float j   = (float)(8 * lane + 1 + k);
        float inv = __fdividef(1.0f, j);
        Aj[k] = 2.0f - inv;
        Bj[k] = 1.0f - inv;
    }

    float p1 = 1.0f, p2 = 0.0f, pp = 1.0f;
    for (int pass = 0; pass < 3; ++pass) {
        float m00 = 1.0f, m01 = 0.0f, m10 = 0.0f, m11 = 1.0f;
#pragma unroll
        for (int k = 0; k < 8; ++k) {
            float a   = Aj[k] * z;
            float n00 = fmaf(a, m00, -Bj[k] * m10);
            float n01 = fmaf(a, m01, -Bj[k] * m11);
            m10 = m00; m11 = m01;
            m00 = n00; m01 = n01;
        }
#pragma unroll
        for (int off = 1; off < 32; off <<= 1) {
            float q00 = __shfl_up_sync(0xffffffffu, m00, off);
            float q01 = __shfl_up_sync(0xffffffffu, m01, off);
            float q10 = __shfl_up_sync(0xffffffffu, m10, off);
            float q11 = __shfl_up_sync(0xffffffffu, m11, off);
            if (lane >= off) {
                float n00 = m00 * q00 + m01 * q10;
                float n01 = m00 * q01 + m01 * q11;
                float n10 = m10 * q00 + m11 * q10;
                float n11 = m10 * q01 + m11 * q11;
                m00 = n00; m01 = n01; m10 = n10; m11 = n11;
            }
        }
        p1 = __shfl_sync(0xffffffffu, m00, 31);
        p2 = __shfl_sync(0xffffffffu, m10, 31);
        pp = 256.0f * (z * p1 - p2) / (z * z - 1.0f);
        z -= p1 / pp;
    }

    if (lane == 0) {
        float wgt = 2.0f / ((1.0f - z * z) * pp * pp);
        float ph  = tanf(0.5f * PI * z);
        g_phi[N_GL - 1 - r] = ph;
        g_phi[r]            = -ph;
        g_w[N_GL - 1 - r]   = wgt;
        g_w[r]              = wgt;
    }
}

// ---------------------------------------------------------------------------
// One node-pass of the gtau recurrence. Accumulate=false stores into the slab,
// accumulate=true adds (second node of the pair).
// ---------------------------------------------------------------------------
template <bool ACC>
__device__ __forceinline__ void gtau_node_pass(
    const float* s_pole, float phi, float w, int lane,
    float* myF, float* myB)
{
    float Etv[NPOLES], Mv[NPOLES], Rv[NPOLES];
    float s_min = 1e30f;
#pragma unroll
    for (int p = 0; p < NPOLES; ++p) {
        float eps = s_pole[p];
        float gam = s_pole[16 + p];
        float a   = s_pole[32 + p];
        float bb  = s_pole[48 + p];

        float om = fmaf(gam, phi, eps);
        float s  = fabsf(om);
        s_min = fminf(s_min, s);
        float numer = 0.25f * w * fmaf(-bb, phi, a);
        float C = numer / (1.0f + __expf(-10.0f * s));
        bool fwd = (om >= 0.0f);
        Rv[p] = fwd ? 1.0f : -1.0f;
        Mv[p] = __expf(-0.32f * s);
        float k = fwd ? (float)lane : (float)(lane + 1);
        Etv[p] = C * __expf(-0.01f * k * s);
    }
    // chunk dead when 0.32*c*s_min > 16  ->  c > 50/s_min
    int myNeed = min(32, (int)(__fdividef(50.0f, s_min)) + 1);

    unsigned long long Et2[NPAIR], M2[NPAIR], R2[NPAIR];
#pragma unroll
    for (int q = 0; q < NPAIR; ++q) {
        Et2[q] = pk2(Etv[q], Etv[q + 8]);
        M2[q]  = pk2(Mv[q],  Mv[q + 8]);
        R2[q]  = pk2(Rv[q],  Rv[q + 8]);
    }

#pragma unroll 2
    for (int c = 0; c < myNeed; ++c) {
        unsigned long long aT2 = 0ull, aS2 = 0ull;
#pragma unroll
        for (int q = 0; q < NPAIR; ++q) {
            aT2 = add2(aT2, Et2[q]);
            aS2 = fma2(R2[q], Et2[q], aS2);
            Et2[q] = mul2(Et2[q], M2[q]);
        }
        float t0, t1, sx0, sx1;
        upk2(aT2, t0, t1);
        upk2(aS2, sx0, sx1);
        float tt = t0 + t1;
        float ss = sx0 + sx1;
        int idx = (c << 5) + lane;
        if (ACC) {
            myF[idx] += tt + ss;
            myB[idx] += tt - ss;
        } else {
            myF[idx] = tt + ss;
            myB[idx] = tt - ss;
        }
    }
    if (!ACC) {
        // clear chunks this pass didn't reach (pass 2 accumulates over all)
        for (int c = myNeed; c < 32; ++c) {
            int idx = (c << 5) + lane;
            myF[idx] = 0.0f;
            myB[idx] = 0.0f;
        }
    }
}

// ---------------------------------------------------------------------------
// Kernel B: 272 static blocks, single wave.
// Blocks 0..255: gtau. Warp = node PAIR (k, k+128): one large-|phi| (fast) +
// one small-|phi| (slow) node -> uniform per-warp work. Private 8KB smem slab
// per warp; pass 1 stores, pass 2 accumulates; block epilogue merges 8 slabs
// and issues 4 REDs per warp slice. Blocks 256..271: Matsubara G0.
// ---------------------------------------------------------------------------
__global__ void __launch_bounds__(256, 3) main_kernel(
    const float* __restrict__ poles_re,
    const float* __restrict__ poles_im,
    const float* __restrict__ res_re,
    const float* __restrict__ res_im,
    float* __restrict__ out)
{
    extern __shared__ float slab[];   // [8 warps][2048]
    __shared__ float s_pole[64];      // staged batch row: eps | gam | a | b
    __shared__ float s_red[8];

    const int t    = threadIdx.x;
    const int lane = t & 31;
    const int wid  = t >> 5;
    const int B    = blockIdx.x;

    if (B < 256) {
        // ------------------------- gtau -----------------------------------
        const int b     = B >> 4;
        const int ngrp  = B & 15;
        const int node1 = (ngrp << 3) + wid;        // 0..127
        const int node2 = node1 + 128;              // 128..255

        if (t < 64) {
            int p = t & 15;
            int which = t >> 4;
            float v;
            if      (which == 0) v =  poles_re[b * NPOLES + p];
            else if (which == 1) v = -poles_im[b * NPOLES + p];
            else if (which == 2) v =  res_re[b * NPOLES + p];
            else                 v =  res_im[b * NPOLES + p];
            s_pole[t] = v;
        }
        __syncthreads();

        float* myF = slab + wid * 2048;
        float* myB = myF + 1024;

        gtau_node_pass<false>(s_pole, g_phi[node1], g_w[node1], lane, myF, myB);
        gtau_node_pass<true>( s_pole, g_phi[node2], g_w[node2], lane, myF, myB);

        __syncthreads();

        // epilogue: warp wid sums 8 slabs over l in [128*wid, +127]
        const int l = (wid << 7) + (lane << 2);
        if (l < LTAU) {
            float ax = 0.f, ay = 0.f, az = 0.f, aw = 0.f;
#pragma unroll
            for (int w2 = 0; w2 < 8; ++w2) {
                const float* base = slab + w2 * 2048;
                float4 f  = *(const float4*)(base + l);
                float4 bq = *(const float4*)(base + 1024 + (996 - l));
                ax += f.x + bq.w;
                ay += f.y + bq.z;
                az += f.z + bq.y;
                aw += f.w + bq.x;
            }
            if (l == 0) ax = 0.0f;        // l==0 belongs to g0
            float* o = out + b * LTAU + l;
            atomicAdd(o + 0, ax);
            atomicAdd(o + 1, ay);
            atomicAdd(o + 2, az);
            atomicAdd(o + 3, aw);
        }
    } else {
        // ------------------------- g0 -------------------------------------
        const int b = B - 256;

        float eps[NPOLES], gam[NPOLES], av[NPOLES], bv[NPOLES];
        float SRc1 = 0.0f, SRc2 = 0.0f, SIc3 = 0.0f, SRc4 = 0.0f, SIc5 = 0.0f;
#pragma unroll
        for (int p = 0; p < NPOLES; ++p) {
            float e =  poles_re[b * NPOLES + p];
            float g = -poles_im[b * NPOLES + p];
            float a =  res_re[b * NPOLES + p];
            float bb = res_im[b * NPOLES + p];
            eps[p] = e; gam[p] = g; av[p] = a; bv[p] = bb;
            float cr = -a, ci = -bb;
            float r2 = cr * e + ci * g, i2 = ci * e - cr * g;
            float r3 = r2 * e + i2 * g, i3 = i2 * e - r2 * g;
            float r4 = r3 * e + i3 * g, i4 = i3 * e - r3 * g;
            float i5 = i4 * e - r4 * g;
            SRc1 += cr; SRc2 += r2; SIc3 += i3; SRc4 += r4; SIc5 += i5;
        }

        const double PI = 3.14159265358979323846;
        const float wn = (float)((2.0 * (double)t + 1.0) * (PI / 10.0));

        float reS = 0.0f;
#pragma unroll
        for (int p = 0; p < NPOLES; ++p) {
            float d = gam[p] + wn;
            reS += (av[p] * eps[p] - bv[p] * d) / (eps[p] * eps[p] + d * d);
        }
        float iw  = 1.0f / wn;
        float iw2 = iw * iw;
        float reG = reS + iw2 * (SRc2 + SIc3 * iw - SRc4 * iw2 - SIc5 * iw2 * iw);

        float acc = reG;
#pragma unroll
        for (int off = 16; off > 0; off >>= 1)
            acc += __shfl_xor_sync(0xffffffffu, acc, off);
        if (lane == 0) s_red[wid] = acc;
        __syncthreads();
        if (t < 8) {
            float v = s_red[t];
#pragma unroll
            for (int off = 4; off > 0; off >>= 1)
                v += __shfl_xor_sync(0xffu, v, off);
            if (t == 0) {
                const float C0 = -0.5f;
                const float C1 = -2.5f;
                const float C2 = (float)(-7.0 * 1.2020569031595942 * 100.0 /
                                         (4.0 * PI * PI * PI));
                const float C3 = (float)(1000.0 / 48.0);
                const float C4 = (float)(31.0 * 1.0369277551433699 * 10000.0 /
                                         (16.0 * PI * PI * PI * PI * PI));
                float G0 = C0 * SRc1 + C1 * SRc2 + C2 * SIc3 + C3 * SRc4
                         + C4 * SIc5 + 0.2f * v;
                out[b * LTAU + 0] = G0;
            }
        }
    }
}

extern "C" void kernel_launch(void* const* d_in, const int* in_sizes, int n_in,
                              void* d_out, int out_size) {
    (void)in_sizes; (void)n_in; (void)out_size;
    const float* pre = (const float*)d_in[0];
    const float* pim = (const float*)d_in[1];
    const float* rre = (const float*)d_in[2];
    const float* rim = (const float*)d_in[3];
    float* out = (float*)d_out;

    static int attr_set = 0;
    if (!attr_set) {
        cudaFuncSetAttribute(main_kernel,
                             cudaFuncAttributeMaxDynamicSharedMemorySize,
                             8 * 2048 * (int)sizeof(float));
        attr_set = 1;
    }

    initzero_kernel<<<10, 512>>>(out);
    main_kernel<<<272, 256, 8 * 2048 * sizeof(float)>>>(pre, pim, rre, rim, out);
}

// round 15
// speedup vs baseline: 1.5453x; 1.0802x over previous
#include <cuda_runtime.h>

#define N_GL    256
#define LTAU    1000
#define BATCH   16
#define NPOLES  16
#define NPAIR   8

// ---- f32x2 packed helpers (sm_103a) ---------------------------------------
__device__ __forceinline__ unsigned long long pk2(float lo, float hi) {
    unsigned long long r;
    asm("mov.b64 %0,{%1,%2};" : "=l"(r) : "f"(lo), "f"(hi));
    return r;
}
__device__ __forceinline__ void upk2(unsigned long long v, float& lo, float& hi) {
    asm("mov.b64 {%0,%1},%2;" : "=f"(lo), "=f"(hi) : "l"(v));
}
__device__ __forceinline__ unsigned long long fma2(unsigned long long a,
                                                   unsigned long long b,
                                                   unsigned long long c) {
    unsigned long long r;
    asm("fma.rn.f32x2 %0,%1,%2,%3;" : "=l"(r) : "l"(a), "l"(b), "l"(c));
    return r;
}
__device__ __forceinline__ unsigned long long mul2(unsigned long long a,
                                                   unsigned long long b) {
    unsigned long long r;
    asm("mul.rn.f32x2 %0,%1,%2;" : "=l"(r) : "l"(a), "l"(b));
    return r;
}
__device__ __forceinline__ unsigned long long add2(unsigned long long a,
                                                   unsigned long long b) {
    unsigned long long r;
    asm("add.rn.f32x2 %0,%1,%2;" : "=l"(r) : "l"(a), "l"(b));
    return r;
}

// ---------------------------------------------------------------------------
// Inline per-warp Gauss-Legendre: the whole warp computes root r (all lanes
// produce identical z; lanes own j-ranges of the Legendre recurrence via a
// 2x2-matrix Kogge-Stone scan). Returns (phi, w) for node n.
// ---------------------------------------------------------------------------
__device__ __forceinline__ void gl_node(int n, int lane, float& phi_out, float& w_out)
{
    const int r = (n < 128) ? n : (255 - n);
    const float PI = 3.14159265358979323846f;
    float z = cosf(PI * ((float)r + 0.75f) / 256.5f);

    float Aj[8], Bj[8];
#pragma unroll
    for (int k = 0; k < 8; ++k) {
        float j   = (float)(8 * lane + 1 + k);
        float inv = __fdividef(1.0f, j);
        Aj[k] = 2.0f - inv;
        Bj[k] = 1.0f - inv;
    }

    float p1 = 1.0f, p2 = 0.0f, pp = 1.0f;
#pragma unroll 1
    for (int pass = 0; pass < 3; ++pass) {
        float m00 = 1.0f, m01 = 0.0f, m10 = 0.0f, m11 = 1.0f;
#pragma unroll
        for (int k = 0; k < 8; ++k) {
            float a   = Aj[k] * z;
            float n00 = fmaf(a, m00, -Bj[k] * m10);
            float n01 = fmaf(a, m01, -Bj[k] * m11);
            m10 = m00; m11 = m01;
            m00 = n00; m01 = n01;
        }
#pragma unroll
        for (int off = 1; off < 32; off <<= 1) {
            float q00 = __shfl_up_sync(0xffffffffu, m00, off);
            float q01 = __shfl_up_sync(0xffffffffu, m01, off);
            float q10 = __shfl_up_sync(0xffffffffu, m10, off);
            float q11 = __shfl_up_sync(0xffffffffu, m11, off);
            if (lane >= off) {
                float n00 = m00 * q00 + m01 * q10;
                float n01 = m00 * q01 + m01 * q11;
                float n10 = m10 * q00 + m11 * q10;
                float n11 = m10 * q01 + m11 * q11;
                m00 = n00; m01 = n01; m10 = n10; m11 = n11;
            }
        }
        p1 = __shfl_sync(0xffffffffu, m00, 31);
        p2 = __shfl_sync(0xffffffffu, m10, 31);
        pp = 256.0f * (z * p1 - p2) / (z * z - 1.0f);
        z -= p1 / pp;
    }

    float wgt = 2.0f / ((1.0f - z * z) * pp * pp);
    float ph  = tanf(0.5f * PI * z);
    phi_out = (n < 128) ? -ph : ph;
    w_out   = wgt;
}

// ---------------------------------------------------------------------------
// Single compute kernel (out pre-zeroed by cudaMemsetAsync).
// Blocks 0..511: gtau. bid -> (g_log = bid>>4, b = bid&15); group permuted
// middle-out so wave-2 bids (>=444) land on extreme-|phi| (fast) node groups.
// Warp = one node (inline GL), private 8KB smem slab, f32x2 T/S-fold
// geometric recurrence, per-warp early exit; epilogue merges 8 slabs, RED to
// gmem, SKIPPING l==0 (owned exclusively by g0 -> no RMW/store race).
// Blocks 512..527: Matsubara G0, plain store to out[b,0].
// ---------------------------------------------------------------------------
__global__ void __launch_bounds__(256, 3) main_kernel(
    const float* __restrict__ poles_re,
    const float* __restrict__ poles_im,
    const float* __restrict__ res_re,
    const float* __restrict__ res_im,
    float* __restrict__ out)
{
    extern __shared__ float slab[];   // [8 warps][2048]
    __shared__ float s_pole[64];      // staged batch row: eps | gam | a | b
    __shared__ float s_red[8];

    const int t    = threadIdx.x;
    const int lane = t & 31;
    const int wid  = t >> 5;
    const int B    = blockIdx.x;

    if (B < 512) {
        // ------------------------- gtau -----------------------------------
        const int g_log = B >> 4;
        const int b     = B & 15;
        const int gphys = (g_log & 1) ? (16 + (g_log >> 1)) : (15 - (g_log >> 1));
        const int node  = (gphys << 3) + wid;

        if (t < 64) {
            int p = t & 15;
            int which = t >> 4;
            float v;
            if      (which == 0) v =  poles_re[b * NPOLES + p];
            else if (which == 1) v = -poles_im[b * NPOLES + p];
            else if (which == 2) v =  res_re[b * NPOLES + p];
            else                 v =  res_im[b * NPOLES + p];
            s_pole[t] = v;
        }

        // inline Gauss-Legendre for this warp's node (overlaps the LDGs above)
        float phi, w;
        gl_node(node, lane, phi, w);

        float* myF = slab + wid * 2048;
        float* myB = myF + 1024;
        {   // zero own slab
            float4* s4 = (float4*)myF;
            const float4 z4 = make_float4(0.f, 0.f, 0.f, 0.f);
#pragma unroll
            for (int i = 0; i < 16; ++i) s4[i * 32 + lane] = z4;
        }
        __syncthreads();

        float Etv[NPOLES], Mv[NPOLES], Rv[NPOLES];
        float s_min = 1e30f;
#pragma unroll
        for (int p = 0; p < NPOLES; ++p) {
            float eps = s_pole[p];
            float gam = s_pole[16 + p];
            float a   = s_pole[32 + p];
            float bb  = s_pole[48 + p];

            float om = fmaf(gam, phi, eps);
            float s  = fabsf(om);
            s_min = fminf(s_min, s);
            float numer = 0.25f * w * fmaf(-bb, phi, a);
            float C = numer / (1.0f + __expf(-10.0f * s));
            bool fwd = (om >= 0.0f);
            Rv[p] = fwd ? 1.0f : -1.0f;
            Mv[p] = __expf(-0.32f * s);
            float k = fwd ? (float)lane : (float)(lane + 1);
            Etv[p] = C * __expf(-0.01f * k * s);
        }
        // chunk dead when 0.32*c*s_min > 16  ->  c > 50/s_min
        int myNeed = min(32, (int)(__fdividef(50.0f, s_min)) + 1);

        unsigned long long Et2[NPAIR], M2[NPAIR], R2[NPAIR];
#pragma unroll
        for (int q = 0; q < NPAIR; ++q) {
            Et2[q] = pk2(Etv[q], Etv[q + 8]);
            M2[q]  = pk2(Mv[q],  Mv[q + 8]);
            R2[q]  = pk2(Rv[q],  Rv[q + 8]);
        }

#pragma unroll 2
        for (int c = 0; c < myNeed; ++c) {
            unsigned long long aT2 = 0ull, aS2 = 0ull;
#pragma unroll
            for (int q = 0; q < NPAIR; ++q) {
                aT2 = add2(aT2, Et2[q]);
                aS2 = fma2(R2[q], Et2[q], aS2);
                Et2[q] = mul2(Et2[q], M2[q]);
            }
            float t0, t1, sx0, sx1;
            upk2(aT2, t0, t1);
            upk2(aS2, sx0, sx1);
            float tt = t0 + t1;
            float ss = sx0 + sx1;
            int idx = (c << 5) + lane;
            myF[idx] = tt + ss;
            myB[idx] = tt - ss;
        }

        __syncthreads();

        // epilogue: warp wid sums 8 slabs over l in [128*wid, +127]
        const int l = (wid << 7) + (lane << 2);
        if (l < LTAU) {
            float ax = 0.f, ay = 0.f, az = 0.f, aw = 0.f;
#pragma unroll
            for (int w2 = 0; w2 < 8; ++w2) {
                const float* base = slab + w2 * 2048;
                float4 f  = *(const float4*)(base + l);
                float4 bq = *(const float4*)(base + 1024 + (996 - l));
                ax += f.x + bq.w;
                ay += f.y + bq.z;
                az += f.z + bq.y;
                aw += f.w + bq.x;
            }
            float* o = out + b * LTAU + l;
            if (l != 0) atomicAdd(o + 0, ax);   // l==0 owned by g0
            atomicAdd(o + 1, ay);
            atomicAdd(o + 2, az);
            atomicAdd(o + 3, aw);
        }
    } else {
        // ------------------------- g0 -------------------------------------
        const int b = B - 512;

        float eps[NPOLES], gam[NPOLES], av[NPOLES], bv[NPOLES];
        float SRc1 = 0.0f, SRc2 = 0.0f, SIc3 = 0.0f, SRc4 = 0.0f, SIc5 = 0.0f;
#pragma unroll
        for (int p = 0; p < NPOLES; ++p) {
            float e =  poles_re[b * NPOLES + p];
            float g = -poles_im[b * NPOLES + p];
            float a =  res_re[b * NPOLES + p];
            float bb = res_im[b * NPOLES + p];
            eps[p] = e; gam[p] = g; av[p] = a; bv[p] = bb;
            float cr = -a, ci = -bb;
            float r2 = cr * e + ci * g, i2 = ci * e - cr * g;
            float r3 = r2 * e + i2 * g, i3 = i2 * e - r2 * g;
            float r4 = r3 * e + i3 * g, i4 = i3 * e - r3 * g;
            float i5 = i4 * e - r4 * g;
            SRc1 += cr; SRc2 += r2; SIc3 += i3; SRc4 += r4; SIc5 += i5;
        }

        const double PI = 3.14159265358979323846;
        const float wn = (float)((2.0 * (double)t + 1.0) * (PI / 10.0));

        float reS = 0.0f;
#pragma unroll
        for (int p = 0; p < NPOLES; ++p) {
            float d = gam[p] + wn;
            reS += (av[p] * eps[p] - bv[p] * d) / (eps[p] * eps[p] + d * d);
        }
        float iw  = 1.0f / wn;
        float iw2 = iw * iw;
        float reG = reS + iw2 * (SRc2 + SIc3 * iw - SRc4 * iw2 - SIc5 * iw2 * iw);

        float acc = reG;
#pragma unroll
        for (int off = 16; off > 0; off >>= 1)
            acc += __shfl_xor_sync(0xffffffffu, acc, off);
        if (lane == 0) s_red[wid] = acc;
        __syncthreads();
        if (t < 8) {
            float v = s_red[t];
#pragma unroll
            for (int off = 4; off > 0; off >>= 1)
                v += __shfl_xor_sync(0xffu, v, off);
            if (t == 0) {
                const float C0 = -0.5f;
                const float C1 = -2.5f;
                const float C2 = (float)(-7.0 * 1.2020569031595942 * 100.0 /
                                         (4.0 * PI * PI * PI));
                const float C3 = (float)(1000.0 / 48.0);
                const float C4 = (float)(31.0 * 1.0369277551433699 * 10000.0 /
                                         (16.0 * PI * PI * PI * PI * PI));
                float G0 = C0 * SRc1 + C1 * SRc2 + C2 * SIc3 + C3 * SRc4
                         + C4 * SIc5 + 0.2f * v;
                out[b * LTAU + 0] = G0;
            }
        }
    }
}

extern "C" void kernel_launch(void* const* d_in, const int* in_sizes, int n_in,
                              void* d_out, int out_size) {
    (void)in_sizes; (void)n_in; (void)out_size;
    const float* pre = (const float*)d_in[0];
    const float* pim = (const float*)d_in[1];
    const float* rre = (const float*)d_in[2];
    const float* rim = (const float*)d_in[3];
    float* out = (float*)d_out;

    static int attr_set = 0;
    if (!attr_set) {
        cudaFuncSetAttribute(main_kernel,
                             cudaFuncAttributeMaxDynamicSharedMemorySize,
                             8 * 2048 * (int)sizeof(float));
        attr_set = 1;
    }

    cudaMemsetAsync(out, 0, BATCH * LTAU * sizeof(float));
    main_kernel<<<528, 256, 8 * 2048 * sizeof(float)>>>(pre, pim, rre, rim, out);
}

// round 16
// speedup vs baseline: 1.5854x; 1.0259x over previous
#include <cuda_runtime.h>

#define N_GL    256
#define LTAU    1000
#define BATCH   16
#define NPOLES  16
#define NPAIR   8

// ---- f32x2 packed helpers (sm_103a) ---------------------------------------
__device__ __forceinline__ unsigned long long pk2(float lo, float hi) {
    unsigned long long r;
    asm("mov.b64 %0,{%1,%2};" : "=l"(r) : "f"(lo), "f"(hi));
    return r;
}
__device__ __forceinline__ void upk2(unsigned long long v, float& lo, float& hi) {
    asm("mov.b64 {%0,%1},%2;" : "=f"(lo), "=f"(hi) : "l"(v));
}
__device__ __forceinline__ unsigned long long fma2(unsigned long long a,
                                                   unsigned long long b,
                                                   unsigned long long c) {
    unsigned long long r;
    asm("fma.rn.f32x2 %0,%1,%2,%3;" : "=l"(r) : "l"(a), "l"(b), "l"(c));
    return r;
}
__device__ __forceinline__ unsigned long long mul2(unsigned long long a,
                                                   unsigned long long b) {
    unsigned long long r;
    asm("mul.rn.f32x2 %0,%1,%2;" : "=l"(r) : "l"(a), "l"(b));
    return r;
}
__device__ __forceinline__ unsigned long long add2(unsigned long long a,
                                                   unsigned long long b) {
    unsigned long long r;
    asm("add.rn.f32x2 %0,%1,%2;" : "=l"(r) : "l"(a), "l"(b));
    return r;
}

// ---------------------------------------------------------------------------
// Inline per-warp Gauss-Legendre (2 Newton passes; initial guess error ~1e-5,
// quadratic convergence puts pass 1 below fp32 noise, pass 2 is margin).
// Lanes own j-ranges of the Legendre recurrence via 2x2-matrix Kogge-Stone.
// ---------------------------------------------------------------------------
__device__ __forceinline__ void gl_node(int n, int lane, float& phi_out, float& w_out)
{
    const int r = (n < 128) ? n : (255 - n);
    const float PI = 3.14159265358979323846f;
    float z = cosf(PI * ((float)r + 0.75f) / 256.5f);

    float Aj[8], Bj[8];
#pragma unroll
    for (int k = 0; k < 8; ++k) {
        float j   = (float)(8 * lane + 1 + k);
        float inv = __fdividef(1.0f, j);
        Aj[k] = 2.0f - inv;
        Bj[k] = 1.0f - inv;
    }

    float p1 = 1.0f, p2 = 0.0f, pp = 1.0f;
#pragma unroll 1
    for (int pass = 0; pass < 2; ++pass) {
        float m00 = 1.0f, m01 = 0.0f, m10 = 0.0f, m11 = 1.0f;
#pragma unroll
        for (int k = 0; k < 8; ++k) {
            float a   = Aj[k] * z;
            float n00 = fmaf(a, m00, -Bj[k] * m10);
            float n01 = fmaf(a, m01, -Bj[k] * m11);
            m10 = m00; m11 = m01;
            m00 = n00; m01 = n01;
        }
#pragma unroll
        for (int off = 1; off < 32; off <<= 1) {
            float q00 = __shfl_up_sync(0xffffffffu, m00, off);
            float q01 = __shfl_up_sync(0xffffffffu, m01, off);
            float q10 = __shfl_up_sync(0xffffffffu, m10, off);
            float q11 = __shfl_up_sync(0xffffffffu, m11, off);
            if (lane >= off) {
                float n00 = m00 * q00 + m01 * q10;
                float n01 = m00 * q01 + m01 * q11;
                float n10 = m10 * q00 + m11 * q10;
                float n11 = m10 * q01 + m11 * q11;
                m00 = n00; m01 = n01; m10 = n10; m11 = n11;
            }
        }
        p1 = __shfl_sync(0xffffffffu, m00, 31);
        p2 = __shfl_sync(0xffffffffu, m10, 31);
        pp = 256.0f * (z * p1 - p2) / (z * z - 1.0f);
        z -= p1 / pp;
    }

    float wgt = 2.0f / ((1.0f - z * z) * pp * pp);
    float ph  = tanf(0.5f * PI * z);
    phi_out = (n < 128) ? -ph : ph;
    w_out   = wgt;
}

// ---------------------------------------------------------------------------
// Single compute kernel (out pre-zeroed by cudaMemsetAsync).
// Blocks 0..15: Matsubara G0 (first -> starts in wave 1; owns out[b,0]).
// Blocks 16..527: gtau. item = B-16 -> (g_log = item>>4, b = item&15); groups
// permuted middle-out so wave-2 bids land on extreme-|phi| (fast) groups.
// Warp = one node (inline GL), private 8KB smem slab, f32x2 T/S-fold
// geometric recurrence, per-warp early exit; epilogue merges 8 slabs, RED to
// gmem, skipping l==0.
// ---------------------------------------------------------------------------
__global__ void __launch_bounds__(256, 3) main_kernel(
    const float* __restrict__ poles_re,
    const float* __restrict__ poles_im,
    const float* __restrict__ res_re,
    const float* __restrict__ res_im,
    float* __restrict__ out)
{
    extern __shared__ float slab[];   // [8 warps][2048]
    __shared__ float s_pole[64];      // staged batch row: eps | gam | a | b
    __shared__ float s_red[8];

    const int t    = threadIdx.x;
    const int lane = t & 31;
    const int wid  = t >> 5;
    const int B    = blockIdx.x;

    if (B >= 16) {
        // ------------------------- gtau -----------------------------------
        const int item  = B - 16;
        const int g_log = item >> 4;
        const int b     = item & 15;
        const int gphys = (g_log & 1) ? (16 + (g_log >> 1)) : (15 - (g_log >> 1));
        const int node  = (gphys << 3) + wid;

        if (t < 64) {
            int p = t & 15;
            int which = t >> 4;
            float v;
            if      (which == 0) v =  poles_re[b * NPOLES + p];
            else if (which == 1) v = -poles_im[b * NPOLES + p];
            else if (which == 2) v =  res_re[b * NPOLES + p];
            else                 v =  res_im[b * NPOLES + p];
            s_pole[t] = v;
        }

        // inline Gauss-Legendre for this warp's node (overlaps the LDGs above)
        float phi, w;
        gl_node(node, lane, phi, w);

        float* myF = slab + wid * 2048;
        float* myB = myF + 1024;
        {   // zero own slab
            float4* s4 = (float4*)myF;
            const float4 z4 = make_float4(0.f, 0.f, 0.f, 0.f);
#pragma unroll
            for (int i = 0; i < 16; ++i) s4[i * 32 + lane] = z4;
        }
        __syncthreads();

        float Etv[NPOLES], Mv[NPOLES], Rv[NPOLES];
        float s_min = 1e30f;
#pragma unroll
        for (int p = 0; p < NPOLES; ++p) {
            float eps = s_pole[p];
            float gam = s_pole[16 + p];
            float a   = s_pole[32 + p];
            float bb  = s_pole[48 + p];

            float om = fmaf(gam, phi, eps);
            float s  = fabsf(om);
            s_min = fminf(s_min, s);
            float numer = 0.25f * w * fmaf(-bb, phi, a);
            float C = numer / (1.0f + __expf(-10.0f * s));
            bool fwd = (om >= 0.0f);
            Rv[p] = fwd ? 1.0f : -1.0f;
            Mv[p] = __expf(-0.32f * s);
            float k = fwd ? (float)lane : (float)(lane + 1);
            Etv[p] = C * __expf(-0.01f * k * s);
        }
        // chunk dead when 0.32*c*s_min > 12  ->  c > 37.5/s_min
        int myNeed = min(32, (int)(__fdividef(37.5f, s_min)) + 1);

        unsigned long long Et2[NPAIR], M2[NPAIR], R2[NPAIR];
#pragma unroll
        for (int q = 0; q < NPAIR; ++q) {
            Et2[q] = pk2(Etv[q], Etv[q + 8]);
            M2[q]  = pk2(Mv[q],  Mv[q + 8]);
            R2[q]  = pk2(Rv[q],  Rv[q + 8]);
        }

#pragma unroll 4
        for (int c = 0; c < myNeed; ++c) {
            unsigned long long aT2 = 0ull, aS2 = 0ull;
#pragma unroll
            for (int q = 0; q < NPAIR; ++q) {
                aT2 = add2(aT2, Et2[q]);
                aS2 = fma2(R2[q], Et2[q], aS2);
                Et2[q] = mul2(Et2[q], M2[q]);
            }
            float t0, t1, sx0, sx1;
            upk2(aT2, t0, t1);
            upk2(aS2, sx0, sx1);
            float tt = t0 + t1;
            float ss = sx0 + sx1;
            int idx = (c << 5) + lane;
            myF[idx] = tt + ss;
            myB[idx] = tt - ss;
        }

        __syncthreads();

        // epilogue: warp wid sums 8 slabs over l in [128*wid, +127]
        const int l = (wid << 7) + (lane << 2);
        if (l < LTAU) {
            float ax = 0.f, ay = 0.f, az = 0.f, aw = 0.f;
#pragma unroll
            for (int w2 = 0; w2 < 8; ++w2) {
                const float* base = slab + w2 * 2048;
                float4 f  = *(const float4*)(base + l);
                float4 bq = *(const float4*)(base + 1024 + (996 - l));
                ax += f.x + bq.w;
                ay += f.y + bq.z;
                az += f.z + bq.y;
                aw += f.w + bq.x;
            }
            float* o = out + b * LTAU + l;
            if (l != 0) atomicAdd(o + 0, ax);   // l==0 owned by g0
            atomicAdd(o + 1, ay);
            atomicAdd(o + 2, az);
            atomicAdd(o + 3, aw);
        }
    } else {
        // ------------------------- g0 -------------------------------------
        const int b = B;

        float eps[NPOLES], gam[NPOLES], av[NPOLES], bv[NPOLES];
        float SRc1 = 0.0f, SRc2 = 0.0f, SIc3 = 0.0f, SRc4 = 0.0f, SIc5 = 0.0f;
#pragma unroll
        for (int p = 0; p < NPOLES; ++p) {
            float e =  poles_re[b * NPOLES + p];
            float g = -poles_im[b * NPOLES + p];
            float a =  res_re[b * NPOLES + p];
            float bb = res_im[b * NPOLES + p];
            eps[p] = e; gam[p] = g; av[p] = a; bv[p] = bb;
            float cr = -a, ci = -bb;
            float r2 = cr * e + ci * g, i2 = ci * e - cr * g;
            float r3 = r2 * e + i2 * g, i3 = i2 * e - r2 * g;
            float r4 = r3 * e + i3 * g, i4 = i3 * e - r3 * g;
            float i5 = i4 * e - r4 * g;
            SRc1 += cr; SRc2 += r2; SIc3 += i3; SRc4 += r4; SIc5 += i5;
        }

        const double PI = 3.14159265358979323846;
        const float wn = (float)((2.0 * (double)t + 1.0) * (PI / 10.0));

        float reS = 0.0f;
#pragma unroll
        for (int p = 0; p < NPOLES; ++p) {
            float d = gam[p] + wn;
            reS += (av[p] * eps[p] - bv[p] * d) / (eps[p] * eps[p] + d * d);
        }
        float iw  = 1.0f / wn;
        float iw2 = iw * iw;
        float reG = reS + iw2 * (SRc2 + SIc3 * iw - SRc4 * iw2 - SIc5 * iw2 * iw);

        float acc = reG;
#pragma unroll
        for (int off = 16; off > 0; off >>= 1)
            acc += __shfl_xor_sync(0xffffffffu, acc, off);
        if (lane == 0) s_red[wid] = acc;
        __syncthreads();
        if (t < 8) {
            float v = s_red[t];
#pragma unroll
            for (int off = 4; off > 0; off >>= 1)
                v += __shfl_xor_sync(0xffu, v, off);
            if (t == 0) {
                const float C0 = -0.5f;
                const float C1 = -2.5f;
                const float C2 = (float)(-7.0 * 1.2020569031595942 * 100.0 /
                                         (4.0 * PI * PI * PI));
                const float C3 = (float)(1000.0 / 48.0);
                const float C4 = (float)(31.0 * 1.0369277551433699 * 10000.0 /
                                         (16.0 * PI * PI * PI * PI * PI));
                float G0 = C0 * SRc1 + C1 * SRc2 + C2 * SIc3 + C3 * SRc4
                         + C4 * SIc5 + 0.2f * v;
                out[b * LTAU + 0] = G0;
            }
        }
    }
}

extern "C" void kernel_launch(void* const* d_in, const int* in_sizes, int n_in,
                              void* d_out, int out_size) {
    (void)in_sizes; (void)n_in; (void)out_size;
    const float* pre = (const float*)d_in[0];
    const float* pim = (const float*)d_in[1];
    const float* rre = (const float*)d_in[2];
    const float* rim = (const float*)d_in[3];
    float* out = (float*)d_out;

    static int attr_set = 0;
    if (!attr_set) {
        cudaFuncSetAttribute(main_kernel,
                             cudaFuncAttributeMaxDynamicSharedMemorySize,
                             8 * 2048 * (int)sizeof(float));
        attr_set = 1;
    }

    cudaMemsetAsync(out, 0, BATCH * LTAU * sizeof(float));
    main_kernel<<<528, 256, 8 * 2048 * sizeof(float)>>>(pre, pim, rre, rim, out);
}